// round 2
// baseline (speedup 1.0000x reference)
#include <cuda_runtime.h>

// StreamingPCEN: EMA over T then pointwise PCEN nonlinearity.
// x: [B=16, MICS=4, T=2048, F=257] f32  ->  out same shape f32.
// Chains = B*MICS*F, recurrence over T. Chunked with decayed warm-up:
// (1-s)^512 ~ 2.4e-6 for s=0.025, far below the 1e-3 rel-err threshold.

#define EPS 1e-6f

constexpr int T  = 2048;
constexpr int F  = 257;
constexpr int BM = 64;          // 16 * 4
constexpr int C  = 4;           // chunks along T
constexpr int L  = T / C;       // 512 output frames per chunk
constexpr int W  = 512;         // warm-up frames (chunks 0,1 exact)

__device__ __forceinline__ float fast_lg2(float x) {
    float y;
    asm("lg2.approx.f32 %0, %1;" : "=f"(y) : "f"(x));
    return y;
}
__device__ __forceinline__ float fast_ex2(float x) {
    float y;
    asm("ex2.approx.f32 %0, %1;" : "=f"(y) : "f"(x));
    return y;
}

__global__ __launch_bounds__(288, 2)
void pcen_kernel(const float* __restrict__ x,
                 const float* __restrict__ sp,
                 const float* __restrict__ alphap,
                 const float* __restrict__ deltap,
                 const float* __restrict__ rp,
                 float* __restrict__ out)
{
    const int f = threadIdx.x;
    if (f >= F) return;
    const int c  = blockIdx.x;
    const int bm = blockIdx.y;

    const float s      = sp[0];
    const float a      = 1.0f - s;
    const float nalpha = -alphap[0];
    const float delta  = deltap[0];
    const float r      = rp[0];

    const size_t chain = (size_t)bm * T * F + f;
    const float* xb = x + chain;
    float*       ob = out + chain;

    const int t0 = c * L;
    const int tw = (c == 0) ? 0 : (t0 - W);

    // m at frame tw (exact when tw == 0, decayed-approx otherwise)
    float m = xb[(size_t)tw * F];

    // ---- warm-up: EMA only, no output ----
    #pragma unroll 8
    for (int t = tw + 1; t < t0; ++t) {
        m = fmaf(a, m, s * xb[(size_t)t * F]);
    }

    const int tend = t0 + L;

    if (r == 0.5f) {
        // sqrt fast path: 2 MUFU (lg2, ex2) + sqrt per element
        const float dr = sqrtf(delta);
        int t = t0;
        if (c == 0) {
            // frame 0: M0 = x0 (no recurrence step)
            float p = fast_ex2(nalpha * fast_lg2(m + EPS));
            float u = fmaf(m, p, delta);
            ob[0] = sqrtf(u) - dr;
            t = 1;
        }
        #pragma unroll 4
        for (; t < tend; ++t) {
            float xv = xb[(size_t)t * F];
            m = fmaf(a, m, s * xv);
            float p = fast_ex2(nalpha * fast_lg2(m + EPS));
            float u = fmaf(xv, p, delta);
            ob[(size_t)t * F] = sqrtf(u) - dr;
        }
    } else {
        const float dr = fast_ex2(r * fast_lg2(delta));
        int t = t0;
        if (c == 0) {
            float p = fast_ex2(nalpha * fast_lg2(m + EPS));
            float u = fmaf(m, p, delta);
            ob[0] = fast_ex2(r * fast_lg2(u)) - dr;
            t = 1;
        }
        #pragma unroll 4
        for (; t < tend; ++t) {
            float xv = xb[(size_t)t * F];
            m = fmaf(a, m, s * xv);
            float p = fast_ex2(nalpha * fast_lg2(m + EPS));
            float u = fmaf(xv, p, delta);
            ob[(size_t)t * F] = fast_ex2(r * fast_lg2(u)) - dr;
        }
    }
}

extern "C" void kernel_launch(void* const* d_in, const int* in_sizes, int n_in,
                              void* d_out, int out_size)
{
    const float* x     = (const float*)d_in[0];
    const float* s     = (const float*)d_in[1];
    const float* alpha = (const float*)d_in[2];
    const float* delta = (const float*)d_in[3];
    const float* r     = (const float*)d_in[4];
    float* out = (float*)d_out;

    dim3 grid(C, BM);
    pcen_kernel<<<grid, 288>>>(x, s, alpha, delta, r, out);
}

// round 3
// speedup vs baseline: 3.5574x; 3.5574x over previous
#include <cuda_runtime.h>

// StreamingPCEN: EMA over T then pointwise PCEN nonlinearity.
// x: [B=16, MICS=4, T=2048, F=257] f32 -> out same shape f32.
// Exact chunked scan: K1 local chunk contributions, K2 serial combine
// over chunk boundaries, K3 replay chunk with exact entry state + output.

#define EPS 1e-6f

constexpr int T  = 2048;
constexpr int F  = 257;
constexpr int BM = 64;          // 16 * 4
constexpr int C  = 32;          // chunks along T
constexpr int L  = T / C;       // 64 frames per chunk
constexpr int NTHREADS = 288;   // covers F=257

// scratch (no cudaMalloc allowed)
__device__ float g_b[C * BM * F];      // local chunk contribution (end state with zero init)
__device__ float g_start[C * BM * F];  // exact entry state M[t0-1] for chunk c>=1

__device__ __forceinline__ float fast_lg2(float x) {
    float y; asm("lg2.approx.f32 %0, %1;" : "=f"(y) : "f"(x)); return y;
}
__device__ __forceinline__ float fast_ex2(float x) {
    float y; asm("ex2.approx.f32 %0, %1;" : "=f"(y) : "f"(x)); return y;
}
__device__ __forceinline__ float fast_sqrt(float x) {
    float y; asm("sqrt.approx.f32 %0, %1;" : "=f"(y) : "f"(x)); return y;
}

// ---- K1: per-chunk local EMA contribution ----
__global__ __launch_bounds__(NTHREADS)
void pcen_k1(const float* __restrict__ x, const float* __restrict__ sp)
{
    const int f = threadIdx.x;
    if (f >= F) return;
    const int c  = blockIdx.x;
    const int bm = blockIdx.y;

    const float s = sp[0];
    const float a = 1.0f - s;

    const float* xb = x + (size_t)bm * T * F + (size_t)c * L * F + f;

    float m;
    int t;
    if (c == 0) { m = xb[0]; t = 1; }        // M_0 = x_0
    else        { m = 0.0f;  t = 0; }        // homogeneous part
    #pragma unroll 8
    for (; t < L; ++t)
        m = fmaf(a, m, s * xb[(size_t)t * F]);

    g_b[((size_t)c * BM + bm) * F + f] = m;
}

// ---- K2: serial combine across chunks (tiny) ----
__global__ __launch_bounds__(NTHREADS)
void pcen_k2(const float* __restrict__ sp)
{
    const int f = threadIdx.x;
    if (f >= F) return;
    const int bm = blockIdx.x;

    const float a = 1.0f - sp[0];
    // aL = a^L via repeated squaring (L = 64 = 2^6)
    float aL = a;
    #pragma unroll
    for (int i = 0; i < 6; ++i) aL *= aL;

    float S = g_b[(size_t)bm * F + f];  // exact end state of chunk 0
    #pragma unroll
    for (int c = 1; c < C; ++c) {
        const size_t idx = ((size_t)c * BM + bm) * F + f;
        g_start[idx] = S;               // M at (c*L - 1)
        S = fmaf(aL, S, g_b[idx]);
    }
}

// ---- K3: replay chunk with exact entry state, emit PCEN output ----
__global__ __launch_bounds__(NTHREADS)
void pcen_k3(const float* __restrict__ x,
             const float* __restrict__ sp,
             const float* __restrict__ alphap,
             const float* __restrict__ deltap,
             const float* __restrict__ rp,
             float* __restrict__ out)
{
    const int f = threadIdx.x;
    if (f >= F) return;
    const int c  = blockIdx.x;
    const int bm = blockIdx.y;

    const float s      = sp[0];
    const float a      = 1.0f - s;
    const float nalpha = -alphap[0];
    const float delta  = deltap[0];
    const float r      = rp[0];

    const size_t base = (size_t)bm * T * F + (size_t)c * L * F + f;
    const float* xb = x + base;
    float*       ob = out + base;

    float m;
    int t;
    if (c == 0) m = xb[0];                                      // M_0 = x_0; emitted below at t=0
    else        m = g_start[((size_t)c * BM + bm) * F + f];     // M[t0-1]

    if (r == 0.5f) {
        const float dr = fast_sqrt(delta);
        t = 0;
        if (c == 0) {
            float p = fast_ex2(nalpha * fast_lg2(m + EPS));
            ob[0] = fast_sqrt(fmaf(m, p, delta)) - dr;
            t = 1;
        }
        #pragma unroll 4
        for (; t < L; ++t) {
            float xv = xb[(size_t)t * F];
            m = fmaf(a, m, s * xv);
            float p = fast_ex2(nalpha * fast_lg2(m + EPS));
            ob[(size_t)t * F] = fast_sqrt(fmaf(xv, p, delta)) - dr;
        }
    } else {
        const float dr = fast_ex2(r * fast_lg2(delta));
        t = 0;
        if (c == 0) {
            float p = fast_ex2(nalpha * fast_lg2(m + EPS));
            ob[0] = fast_ex2(r * fast_lg2(fmaf(m, p, delta))) - dr;
            t = 1;
        }
        #pragma unroll 4
        for (; t < L; ++t) {
            float xv = xb[(size_t)t * F];
            m = fmaf(a, m, s * xv);
            float p = fast_ex2(nalpha * fast_lg2(m + EPS));
            ob[(size_t)t * F] = fast_ex2(r * fast_lg2(fmaf(xv, p, delta))) - dr;
        }
    }
}

extern "C" void kernel_launch(void* const* d_in, const int* in_sizes, int n_in,
                              void* d_out, int out_size)
{
    const float* x     = (const float*)d_in[0];
    const float* s     = (const float*)d_in[1];
    const float* alpha = (const float*)d_in[2];
    const float* delta = (const float*)d_in[3];
    const float* r     = (const float*)d_in[4];
    float* out = (float*)d_out;

    dim3 grid(C, BM);
    pcen_k1<<<grid, NTHREADS>>>(x, s);
    pcen_k2<<<BM, NTHREADS>>>(s);
    pcen_k3<<<grid, NTHREADS>>>(x, s, alpha, delta, r, out);
}